// round 1
// baseline (speedup 1.0000x reference)
#include <cuda_runtime.h>
#include <math.h>

#define Bz 64
#define Pz 196
#define Dz 512
#define Vz 10000
#define MAXLEN 52
#define Tz 51
#define G4 2048

static const long long OFF_CAPS = (long long)Bz * Tz * Vz;            // 32640000
static const long long OFF_DEC  = OFF_CAPS + (long long)Bz * MAXLEN;  // 32643328
static const long long OFF_SI   = OFF_DEC + Bz;                       // 32643392

// ------------------------- device scratch (no allocs allowed) -------------
__device__ float d_enc_s[Bz * Pz * Dz];
__device__ float d_att1[Bz * Pz * Dz];
__device__ float d_cls[Bz * Dz];
__device__ float d_h[Bz * Dz];
__device__ float d_c[Bz * Dz];
__device__ float d_hg[Bz * 1024];      // [att2 | gate-logit]
__device__ float d_awe[Bz * Dz];
__device__ float d_pre[Tz * Bz * G4];
__device__ float d_clspre[Bz * G4];
__device__ float d_gates[Bz * G4];
__device__ float d_Hall[Tz * Bz * Dz];
__device__ float d_WihT[1536 * G4];    // WihT[k][j] = Wih[j][k]
__device__ float d_WhhT[Dz * G4];
__device__ float d_embs[Tz * Bz * Dz]; // row r = t*64+b
__device__ int   d_sort[Bz];
__device__ int   d_dec[Bz];
__device__ int   d_caps[Bz * MAXLEN];

__device__ __forceinline__ float sigf(float x) { return 1.f / (1.f + __expf(-x)); }

// ------------------------- setup kernels ----------------------------------
__global__ void k_sort(const int* __restrict__ cap_len, float* __restrict__ out,
                       long long out_size) {
    __shared__ int ls[Bz];
    int tid = threadIdx.x;
    ls[tid] = cap_len[tid];
    __syncthreads();
    int my = ls[tid];
    int rank = 0;
    for (int j = 0; j < Bz; j++) {
        int lj = ls[j];
        if (lj > my || (lj == my && j < tid)) rank++;
    }
    d_sort[rank] = tid;
    d_dec[rank]  = my - 1;
    if (OFF_SI + Bz <= out_size) {
        out[OFF_DEC + rank] = (float)(my - 1);
        out[OFF_SI + rank]  = (float)tid;
    }
}

__global__ void k_gather_enc(const float* __restrict__ enc_in) {
    int n = Bz * Pz * Dz;
    for (int idx = blockIdx.x * blockDim.x + threadIdx.x; idx < n;
         idx += gridDim.x * blockDim.x) {
        int b = idx / (Pz * Dz);
        int r = idx - b * (Pz * Dz);
        d_enc_s[idx] = enc_in[(long long)d_sort[b] * (Pz * Dz) + r];
    }
}

__global__ void k_gather_misc(const int* __restrict__ caps_in,
                              const int* __restrict__ class_k,
                              const float* __restrict__ clsW,
                              float* __restrict__ out, long long out_size) {
    int b = blockIdx.x;
    int e = threadIdx.x;  // 512 threads
    d_cls[b * Dz + e] = clsW[(long long)class_k[b] * Dz + e];
    if (e < MAXLEN) {
        int v = caps_in[d_sort[b] * MAXLEN + e];
        d_caps[b * MAXLEN + e] = v;
        if (OFF_CAPS + (long long)Bz * MAXLEN <= out_size)
            out[OFF_CAPS + b * MAXLEN + e] = (float)v;
    }
}

__global__ void k_init(const float* __restrict__ ihW, const float* __restrict__ ihb,
                       const float* __restrict__ icW, const float* __restrict__ icb) {
    __shared__ float s[1024];
    int b = blockIdx.x, j = threadIdx.x;  // 512 threads
    float sum = 0.f;
    for (int p = 0; p < Pz; p++) sum += d_enc_s[(b * Pz + p) * Dz + j];
    s[j] = sum * (1.f / 196.f);
    s[Dz + j] = d_cls[b * Dz + j];
    __syncthreads();
    float ah = ihb[j], ac = icb[j];
    for (int k = 0; k < 1024; k++) {
        float x = s[k];
        ah = fmaf(x, ihW[k * Dz + j], ah);
        ac = fmaf(x, icW[k * Dz + j], ac);
    }
    d_h[b * Dz + j] = ah;
    d_c[b * Dz + j] = ac;
}

__global__ void k_embs(const float* __restrict__ embW) {
    int n = Tz * Bz * Dz;
    for (int idx = blockIdx.x * blockDim.x + threadIdx.x; idx < n;
         idx += gridDim.x * blockDim.x) {
        int r = idx / Dz, k = idx - r * Dz;
        int t = r >> 6, b = r & 63;
        int tok = d_caps[b * MAXLEN + t];
        d_embs[idx] = embW[(long long)tok * Dz + k];
    }
}

__global__ void k_transpose(const float* __restrict__ Wih,
                            const float* __restrict__ Whh) {
    int n1 = 1536 * G4;
    int n = n1 + Dz * G4;
    for (int idx = blockIdx.x * blockDim.x + threadIdx.x; idx < n;
         idx += gridDim.x * blockDim.x) {
        if (idx < n1) {
            int k = idx / G4, j = idx - k * G4;
            d_WihT[idx] = Wih[(long long)j * 1536 + k];
        } else {
            int i2 = idx - n1;
            int k = i2 / G4, j = i2 - k * G4;
            d_WhhT[i2] = Whh[(long long)j * Dz + k];
        }
    }
}

__global__ void k_preadd(const float* __restrict__ bih, const float* __restrict__ bhh) {
    int n = Tz * Bz * G4;
    for (int idx = blockIdx.x * blockDim.x + threadIdx.x; idx < n;
         idx += gridDim.x * blockDim.x) {
        int j = idx & (G4 - 1);
        int b = (idx >> 11) & 63;
        d_pre[idx] += d_clspre[b * G4 + j] + bih[j] + bhh[j];
    }
}

// ------------------------- generic 128x128 fp32 GEMM -----------------------
// C[M,N] = A[M,K] @ B[K,N] (+bias). mode==1: fc epilogue (mask + reorder -> out).
__global__ void __launch_bounds__(256) gemm128(
    const float* __restrict__ A, int lda, const float* __restrict__ Bm, int ldb,
    const float* __restrict__ bias, float* __restrict__ C, int ldc,
    int M, int N, int K, int mode, float* __restrict__ outp) {
    __shared__ float As[8][128];
    __shared__ float Bs[8][128];
    int tid = threadIdx.x;
    int n0 = blockIdx.x * 128, m0 = blockIdx.y * 128;
    int tx = tid & 15, ty = tid >> 4;
    float acc[8][8];
#pragma unroll
    for (int i = 0; i < 8; i++)
#pragma unroll
        for (int j = 0; j < 8; j++) acc[i][j] = 0.f;

    int lm = tid >> 1;
    int lkq = (tid & 1) * 4;
    int lk = tid >> 5;
    int ln4 = (tid & 31) * 4;

    for (int k0 = 0; k0 < K; k0 += 8) {
        float4 va = make_float4(0.f, 0.f, 0.f, 0.f);
        int gm = m0 + lm;
        if (gm < M) va = *(const float4*)(A + (long long)gm * lda + k0 + lkq);
        float4 vb;
        int gn = n0 + ln4;
        const float* bp = Bm + (long long)(k0 + lk) * ldb + gn;
        if (gn + 3 < N) {
            vb = *(const float4*)bp;
        } else {
            vb.x = (gn + 0 < N) ? bp[0] : 0.f;
            vb.y = (gn + 1 < N) ? bp[1] : 0.f;
            vb.z = (gn + 2 < N) ? bp[2] : 0.f;
            vb.w = (gn + 3 < N) ? bp[3] : 0.f;
        }
        __syncthreads();
        As[lkq + 0][lm] = va.x;
        As[lkq + 1][lm] = va.y;
        As[lkq + 2][lm] = va.z;
        As[lkq + 3][lm] = va.w;
        *(float4*)&Bs[lk][ln4] = vb;
        __syncthreads();
#pragma unroll
        for (int kk = 0; kk < 8; kk++) {
            float4 A0 = *(const float4*)&As[kk][ty * 8];
            float4 A1 = *(const float4*)&As[kk][ty * 8 + 4];
            float4 B0 = *(const float4*)&Bs[kk][tx * 8];
            float4 B1 = *(const float4*)&Bs[kk][tx * 8 + 4];
            float ar[8] = {A0.x, A0.y, A0.z, A0.w, A1.x, A1.y, A1.z, A1.w};
            float br[8] = {B0.x, B0.y, B0.z, B0.w, B1.x, B1.y, B1.z, B1.w};
#pragma unroll
            for (int i = 0; i < 8; i++)
#pragma unroll
                for (int j = 0; j < 8; j++) acc[i][j] = fmaf(ar[i], br[j], acc[i][j]);
        }
    }

#pragma unroll
    for (int i = 0; i < 8; i++) {
        int gm = m0 + ty * 8 + i;
        if (gm >= M) continue;
#pragma unroll
        for (int j = 0; j < 8; j++) {
            int gn = n0 + tx * 8 + j;
            if (gn >= N) continue;
            float v = acc[i][j] + (bias ? bias[gn] : 0.f);
            if (mode == 0) {
                C[(long long)gm * ldc + gn] = v;
            } else {
                int tt = gm >> 6, bb = gm & 63;
                if (tt >= d_dec[bb]) v = 0.f;
                outp[((long long)bb * Tz + tt) * Vz + gn] = v;
            }
        }
    }
}

// ------------------------- per-step kernels --------------------------------
// hg[b][0:512] = h@dec_att_W + dec_att_b ; hg[b][512:1024] = h@f_beta_W + f_beta_b
__global__ void __launch_bounds__(256) k_hproj(const float* __restrict__ daW,
                                               const float* __restrict__ dab,
                                               const float* __restrict__ fbW,
                                               const float* __restrict__ fbb) {
    __shared__ float hs[8 * Dz];
    int j0 = blockIdx.x * 64;
    int b0 = blockIdx.y * 8;
    int tid = threadIdx.x;
    for (int i = tid; i < (8 * Dz) / 4; i += 256)
        ((float4*)hs)[i] = ((const float4*)(d_h + b0 * Dz))[i];
    __syncthreads();
    int jl = tid & 63, bq = tid >> 6;
    int j = j0 + jl;
    const float* W;
    float bias;
    if (j < Dz) { W = daW + j; bias = dab[j]; }
    else        { W = fbW + (j - Dz); bias = fbb[j - Dz]; }
    float a0 = bias, a1 = bias;
    for (int k = 0; k < Dz; k++) {
        float w = W[k * Dz];
        a0 = fmaf(hs[bq * Dz + k], w, a0);
        a1 = fmaf(hs[(bq + 4) * Dz + k], w, a1);
    }
    d_hg[(b0 + bq) * 1024 + j] = a0;
    d_hg[(b0 + bq + 4) * 1024 + j] = a1;
}

__global__ void __launch_bounds__(256) k_attn(const float* __restrict__ faw,
                                              const float* __restrict__ fabp) {
    __shared__ float att2s[Dz];
    __shared__ float ws[Dz];
    __shared__ float es[Pz];
    __shared__ float red[8];
    int b = blockIdx.x, tid = threadIdx.x;
    int wp = tid >> 5, ln = tid & 31;
    float fab = fabp[0];
    for (int i = tid; i < Dz; i += 256) {
        att2s[i] = d_hg[b * 1024 + i];
        ws[i] = faw[i];
    }
    __syncthreads();
    for (int p = wp; p < Pz; p += 8) {
        const float* row = d_att1 + (long long)(b * Pz + p) * Dz;
        float s = 0.f;
        for (int a = ln; a < Dz; a += 32)
            s = fmaf(fmaxf(row[a] + att2s[a], 0.f), ws[a], s);
#pragma unroll
        for (int o = 16; o > 0; o >>= 1) s += __shfl_down_sync(0xffffffffu, s, o);
        if (ln == 0) es[p] = s + fab;
    }
    __syncthreads();
    // softmax over 196
    float v = (tid < Pz) ? es[tid] : -3.4e38f;
#pragma unroll
    for (int o = 16; o > 0; o >>= 1) v = fmaxf(v, __shfl_down_sync(0xffffffffu, v, o));
    if (ln == 0) red[wp] = v;
    __syncthreads();
    if (tid == 0) {
        float m = red[0];
        for (int i = 1; i < 8; i++) m = fmaxf(m, red[i]);
        red[0] = m;
    }
    __syncthreads();
    float MX = red[0];
    float ex = (tid < Pz) ? __expf(es[tid] - MX) : 0.f;
    __syncthreads();
    float s = ex;
#pragma unroll
    for (int o = 16; o > 0; o >>= 1) s += __shfl_down_sync(0xffffffffu, s, o);
    if (ln == 0) red[wp] = s;
    __syncthreads();
    if (tid == 0) {
        float t2 = 0.f;
        for (int i = 0; i < 8; i++) t2 += red[i];
        red[0] = t2;
    }
    __syncthreads();
    float inv = 1.f / red[0];
    if (tid < Pz) es[tid] = ex * inv;
    __syncthreads();
    // awe + gate
    for (int e = tid; e < Dz; e += 256) {
        float a = 0.f;
        for (int p = 0; p < Pz; p++)
            a = fmaf(d_enc_s[(long long)(b * Pz + p) * Dz + e], es[p], a);
        float g = sigf(d_hg[b * 1024 + Dz + e]);
        d_awe[b * Dz + e] = g * a;
    }
}

__global__ void __launch_bounds__(256) k_lstm(int t) {
    __shared__ float as_[8 * Dz];
    __shared__ float hs[8 * Dz];
    int j0 = blockIdx.x * 64;
    int b0 = blockIdx.y * 8;
    int tid = threadIdx.x;
    for (int i = tid; i < (8 * Dz) / 4; i += 256) {
        ((float4*)as_)[i] = ((const float4*)(d_awe + b0 * Dz))[i];
        ((float4*)hs)[i] = ((const float4*)(d_h + b0 * Dz))[i];
    }
    __syncthreads();
    int jl = tid & 63, bq = tid >> 6;
    int j = j0 + jl;
    const float* wa = d_WihT + (long long)Dz * G4 + j;  // awe block of Wih^T
    const float* wh = d_WhhT + j;
    float a0 = 0.f, a1 = 0.f;
    for (int k = 0; k < Dz; k++) {
        float w1 = wa[(long long)k * G4];
        float w2 = wh[(long long)k * G4];
        a0 = fmaf(as_[bq * Dz + k], w1, a0);
        a0 = fmaf(hs[bq * Dz + k], w2, a0);
        a1 = fmaf(as_[(bq + 4) * Dz + k], w1, a1);
        a1 = fmaf(hs[(bq + 4) * Dz + k], w2, a1);
    }
    int r0 = t * Bz + b0 + bq;
    int r1 = t * Bz + b0 + bq + 4;
    d_gates[(b0 + bq) * G4 + j] = d_pre[(long long)r0 * G4 + j] + a0;
    d_gates[(b0 + bq + 4) * G4 + j] = d_pre[(long long)r1 * G4 + j] + a1;
}

__global__ void k_cell(int t) {
    int b = blockIdx.x, j = threadIdx.x;  // 512 threads
    const float* g = d_gates + b * G4;
    float i_ = sigf(g[j]);
    float f_ = sigf(g[Dz + j]);
    float gg = tanhf(g[2 * Dz + j]);
    float o_ = sigf(g[3 * Dz + j]);
    float c0 = d_c[b * Dz + j];
    float cn = f_ * c0 + i_ * gg;
    float hn = o_ * tanhf(cn);
    d_Hall[(long long)(t * Bz + b) * Dz + j] = hn;
    bool act = t < d_dec[b];
    if (act) {
        d_h[b * Dz + j] = hn;
        d_c[b * Dz + j] = cn;
    }
}

// ------------------------- host launcher -----------------------------------
extern "C" void kernel_launch(void* const* d_in, const int* in_sizes, int n_in,
                              void* d_out, int out_size) {
    const float* enc_out = (const float*)d_in[0];
    const int* caps_in = (const int*)d_in[1];
    const int* cap_len = (const int*)d_in[2];
    const int* class_k = (const int*)d_in[3];
    const float* embW = (const float*)d_in[4];
    const float* clsW = (const float*)d_in[5];
    const float* eaW = (const float*)d_in[6];
    const float* eab = (const float*)d_in[7];
    const float* daW = (const float*)d_in[8];
    const float* dab = (const float*)d_in[9];
    const float* faw = (const float*)d_in[10];
    const float* fab = (const float*)d_in[11];
    const float* ihW = (const float*)d_in[12];
    const float* ihb = (const float*)d_in[13];
    const float* icW = (const float*)d_in[14];
    const float* icb = (const float*)d_in[15];
    const float* fbW = (const float*)d_in[16];
    const float* fbb = (const float*)d_in[17];
    const float* Wih = (const float*)d_in[18];
    const float* Whh = (const float*)d_in[19];
    const float* bih = (const float*)d_in[20];
    const float* bhh = (const float*)d_in[21];
    const float* fcW = (const float*)d_in[22];
    const float* fcb = (const float*)d_in[23];
    float* out = (float*)d_out;
    long long osz = out_size;

    float *p_enc_s, *p_att1, *p_embs, *p_WihT, *p_pre, *p_cls, *p_clspre, *p_Hall;
    cudaGetSymbolAddress((void**)&p_enc_s, d_enc_s);
    cudaGetSymbolAddress((void**)&p_att1, d_att1);
    cudaGetSymbolAddress((void**)&p_embs, d_embs);
    cudaGetSymbolAddress((void**)&p_WihT, d_WihT);
    cudaGetSymbolAddress((void**)&p_pre, d_pre);
    cudaGetSymbolAddress((void**)&p_cls, d_cls);
    cudaGetSymbolAddress((void**)&p_clspre, d_clspre);
    cudaGetSymbolAddress((void**)&p_Hall, d_Hall);

    k_sort<<<1, Bz>>>(cap_len, out, osz);
    k_gather_enc<<<(Bz * Pz * Dz + 255) / 256, 256>>>(enc_out);
    k_gather_misc<<<Bz, Dz>>>(caps_in, class_k, clsW, out, osz);
    k_init<<<Bz, Dz>>>(ihW, ihb, icW, icb);

    // att1 = enc_s @ enc_att_W + b : [12544,512]
    gemm128<<<dim3(4, 98), 256>>>(p_enc_s, Dz, eaW, Dz, eab, p_att1, Dz,
                                  Bz * Pz, Dz, Dz, 0, nullptr);

    k_embs<<<(Tz * Bz * Dz + 255) / 256, 256>>>(embW);
    k_transpose<<<(1536 * G4 + Dz * G4 + 255) / 256, 256>>>(Wih, Whh);

    // pre_gates = embs @ WihT[0:512] : [3264,2048]
    gemm128<<<dim3(16, 26), 256>>>(p_embs, Dz, p_WihT, G4, nullptr, p_pre, G4,
                                   Tz * Bz, G4, Dz, 0, nullptr);
    // cls_pre = cls_emb @ WihT[1024:1536] : [64,2048]
    gemm128<<<dim3(16, 1), 256>>>(p_cls, Dz, p_WihT + (long long)1024 * G4, G4,
                                  nullptr, p_clspre, G4, Bz, G4, Dz, 0, nullptr);
    k_preadd<<<(Tz * Bz * G4 + 255) / 256, 256>>>(bih, bhh);

    for (int t = 0; t < Tz; t++) {
        k_hproj<<<dim3(16, 8), 256>>>(daW, dab, fbW, fbb);
        k_attn<<<Bz, 256>>>(faw, fab);
        k_lstm<<<dim3(32, 8), 256>>>(t);
        k_cell<<<Bz, Dz>>>(t);
    }

    // predictions = mask(Hall @ fc_W + fc_b), reordered [b,t,v] into out
    gemm128<<<dim3(79, 26), 256>>>(p_Hall, Dz, fcW, Vz, fcb, nullptr, 0,
                                   Tz * Bz, Vz, Dz, 1, out);
}